// round 5
// baseline (speedup 1.0000x reference)
#include <cuda_runtime.h>
#include <cstdint>

// ComplexBlockLinear, mma.sync tf32, Karatsuba 3-mult complex GEMM,
// cp.async double-buffered. CTA = 64 rows x 1 block (128 cols), 8 warps
// (2 M x 4 N), warp tile 32x32. K chunked by 16.
// t1=xr@wr, t2=xi@wi, t3=(xr+xi)@(wr+wi); re=t1-t2, im=t3-t1-t2.

#define NBLK 8
#define BS 128
#define HD 1024
#define CTA_M 64
#define KC 16
#define NCHUNK (BS / KC)     // 8
#define THREADS 256

// smem floats per stage: XR 64x20, XI 64x20, WW 16x264
#define XSTR 20
#define WSTR 264
#define XR_OFF 0
#define XI_OFF 5120
#define WW_OFF 10240
#define STAGE_BYTES 27136
#define SMEM_TOTAL (2 * STAGE_BYTES)   // 54272

__device__ __forceinline__ unsigned f2tf(float x) {
    unsigned u;
    asm("cvt.rna.tf32.f32 %0, %1;" : "=r"(u) : "f"(x));
    return u;
}
__device__ __forceinline__ uint32_t smem_u32(const void* p) {
    uint32_t a;
    asm("{ .reg .u64 t; cvta.to.shared.u64 t, %1; cvt.u32.u64 %0, t; }"
        : "=r"(a) : "l"(p));
    return a;
}
__device__ __forceinline__ void cp16(uint32_t dst, const void* src) {
    asm volatile("cp.async.ca.shared.global [%0], [%1], 16;"
                 :: "r"(dst), "l"(src) : "memory");
}
__device__ __forceinline__ void cp_commit() {
    asm volatile("cp.async.commit_group;" ::: "memory");
}
template <int N>
__device__ __forceinline__ void cp_wait() {
    asm volatile("cp.async.wait_group %0;" :: "n"(N) : "memory");
}
__device__ __forceinline__ void mma_tf32(float* d, const unsigned* a,
                                         unsigned b0, unsigned b1) {
    asm volatile(
        "mma.sync.aligned.m16n8k8.row.col.f32.tf32.tf32.f32 "
        "{%0,%1,%2,%3},{%4,%5,%6,%7},{%8,%9},{%0,%1,%2,%3};\n"
        : "+f"(d[0]), "+f"(d[1]), "+f"(d[2]), "+f"(d[3])
        : "r"(a[0]), "r"(a[1]), "r"(a[2]), "r"(a[3]), "r"(b0), "r"(b1));
}

__global__ __launch_bounds__(THREADS)
void cbl_kar_kernel(const float* __restrict__ xre,
                    const float* __restrict__ xim,
                    const float* __restrict__ w,
                    float* __restrict__ out) {
    extern __shared__ char smem[];
    const uint32_t sb = smem_u32(smem);

    const int tid  = threadIdx.x;
    const int lane = tid & 31;
    const int warp = tid >> 5;
    const int wm   = warp >> 2;    // 0..1
    const int wn   = warp & 3;     // 0..3

    const int row0 = blockIdx.x * CTA_M;
    const int nb   = blockIdx.y;

    // X staging: 64 rows x 16 k = 256 16B-chunks per array, 1 per thread
    const int xs_r = tid >> 2;            // 0..63
    const float* xr_src0 = xre + (size_t)(row0 + xs_r) * HD + nb * BS + (tid & 3) * 4;
    const float* xi_src0 = xim + (size_t)(row0 + xs_r) * HD + nb * BS + (tid & 3) * 4;
    const uint32_t x_dst_off = xs_r * (XSTR * 4) + (tid & 3) * 16;

    float t1[2][4][4], t2[2][4][4], t3[2][4][4];
#pragma unroll
    for (int a = 0; a < 2; a++)
#pragma unroll
        for (int b = 0; b < 4; b++)
#pragma unroll
            for (int c = 0; c < 4; c++) {
                t1[a][b][c] = 0.f; t2[a][b][c] = 0.f; t3[a][b][c] = 0.f;
            }

    auto issue = [&](int c) {
        const uint32_t base = sb + (c & 1) * STAGE_BYTES;
        const int k0 = c * KC;
        cp16(base + XR_OFF + x_dst_off, xr_src0 + k0);
        cp16(base + XI_OFF + x_dst_off, xi_src0 + k0);
        // W: 16 k-rows x 64 chunks (16B = 2 complex) = 1024 chunks, 4/thread
#pragma unroll
        for (int q = 0; q < 4; ++q) {
            const int e  = q * THREADS + tid;   // 0..1023
            const int kk = e >> 6;              // 0..15
            const int oc = e & 63;              // 0..63
            const float* src = w +
                ((size_t)((nb * BS + k0 + kk) * BS) + oc * 2) * 2;
            cp16(base + WW_OFF + kk * (WSTR * 4) + oc * 16, src);
        }
        cp_commit();
    };

    issue(0);

#pragma unroll 1
    for (int c = 0; c < NCHUNK; ++c) {
        if (c + 1 < NCHUNK) { issue(c + 1); cp_wait<1>(); }
        else                { cp_wait<0>(); }
        __syncthreads();

        const float* sXR = (const float*)(smem + (c & 1) * STAGE_BYTES + XR_OFF);
        const float* sXI = (const float*)(smem + (c & 1) * STAGE_BYTES + XI_OFF);
        const float* sWW = (const float*)(smem + (c & 1) * STAGE_BYTES + WW_OFF);

#pragma unroll
        for (int ks = 0; ks < KC / 8; ++ks) {
            const int kk = ks * 8;
            unsigned ar[2][4], ai[2][4], as_[2][4];
#pragma unroll
            for (int mt = 0; mt < 2; ++mt) {
                const int rr = wm * 32 + mt * 16 + (lane >> 2);
                const int cc = kk + (lane & 3);
                float fr[4], fi[4];
                fr[0] = sXR[rr * XSTR + cc];
                fr[1] = sXR[(rr + 8) * XSTR + cc];
                fr[2] = sXR[rr * XSTR + cc + 4];
                fr[3] = sXR[(rr + 8) * XSTR + cc + 4];
                fi[0] = sXI[rr * XSTR + cc];
                fi[1] = sXI[(rr + 8) * XSTR + cc];
                fi[2] = sXI[rr * XSTR + cc + 4];
                fi[3] = sXI[(rr + 8) * XSTR + cc + 4];
#pragma unroll
                for (int j = 0; j < 4; ++j) {
                    ar[mt][j]  = f2tf(fr[j]);
                    ai[mt][j]  = f2tf(fi[j]);
                    as_[mt][j] = f2tf(fr[j] + fi[j]);
                }
            }
#pragma unroll
            for (int nt = 0; nt < 4; ++nt) {
                const int n  = wn * 32 + nt * 8 + (lane >> 2);
                const int kb = kk + (lane & 3);
                const float2 p0 = *(const float2*)&sWW[kb * WSTR + n * 2];
                const float2 p1 = *(const float2*)&sWW[(kb + 4) * WSTR + n * 2];
                const unsigned br0 = f2tf(p0.x);
                const unsigned bi0 = f2tf(p0.y);
                const unsigned bs0 = f2tf(p0.x + p0.y);
                const unsigned br1 = f2tf(p1.x);
                const unsigned bi1 = f2tf(p1.y);
                const unsigned bs1 = f2tf(p1.x + p1.y);
#pragma unroll
                for (int mt = 0; mt < 2; ++mt) {
                    mma_tf32(t1[mt][nt], ar[mt],  br0, br1);
                    mma_tf32(t2[mt][nt], ai[mt],  bi0, bi1);
                    mma_tf32(t3[mt][nt], as_[mt], bs0, bs1);
                }
            }
        }
        __syncthreads();
    }

    // epilogue: re = t1 - t2; im = t3 - t1 - t2; interleaved float4 stores
#pragma unroll
    for (int mt = 0; mt < 2; ++mt) {
        const int r_lo = row0 + wm * 32 + mt * 16 + (lane >> 2);
#pragma unroll
        for (int nt = 0; nt < 4; ++nt) {
            const int col = nb * BS + wn * 32 + nt * 8 + (lane & 3) * 2;
            float re0 = t1[mt][nt][0] - t2[mt][nt][0];
            float im0 = t3[mt][nt][0] - t1[mt][nt][0] - t2[mt][nt][0];
            float re1 = t1[mt][nt][1] - t2[mt][nt][1];
            float im1 = t3[mt][nt][1] - t1[mt][nt][1] - t2[mt][nt][1];
            float re2 = t1[mt][nt][2] - t2[mt][nt][2];
            float im2 = t3[mt][nt][2] - t1[mt][nt][2] - t2[mt][nt][2];
            float re3 = t1[mt][nt][3] - t2[mt][nt][3];
            float im3 = t3[mt][nt][3] - t1[mt][nt][3] - t2[mt][nt][3];
            *(float4*)(out + ((size_t)r_lo * HD + col) * 2) =
                make_float4(re0, im0, re1, im1);
            *(float4*)(out + ((size_t)(r_lo + 8) * HD + col) * 2) =
                make_float4(re2, im2, re3, im3);
        }
    }
}

extern "C" void kernel_launch(void* const* d_in, const int* in_sizes, int n_in,
                              void* d_out, int out_size) {
    const float* xre = (const float*)d_in[0];
    const float* xim = (const float*)d_in[1];
    const float* w   = (const float*)d_in[2];
    float* out       = (float*)d_out;

    cudaFuncSetAttribute(cbl_kar_kernel,
                         cudaFuncAttributeMaxDynamicSharedMemorySize, SMEM_TOTAL);
    dim3 grid(32768 / CTA_M, NBLK);   // (512, 8)
    cbl_kar_kernel<<<grid, THREADS, SMEM_TOTAL>>>(xre, xim, w, out);
}